// round 4
// baseline (speedup 1.0000x reference)
#include <cuda_runtime.h>
#include <math_constants.h>

#define NN 50000
#define EE 800000
#define DD 128
#define ET (EE + NN)
#define NB ((NN + 255) / 256)   // 196 scan blocks
#define BN_EPS 1e-12f
#define SLOPE 0.2f

// ---------------- scratch (static device globals; no allocation) ----------------
__device__ __align__(16) float g_h [NN * DD];   // h = x @ W (per layer)
__device__ __align__(16) float g_x1[NN * DD];   // layer-1 output
__device__ float g_hs[NN];                      // h @ a_src
__device__ float g_hd[NN];                      // h @ a_dst
__device__ int   g_cnt[NN];                     // in-degree (incl. self loop)
__device__ int   g_rowoff[NN + 1];              // CSR row offsets
__device__ int   g_fill[NN];                    // scatter cursors
__device__ int   g_bsum[256];                   // scan block sums
__device__ int   g_csr[ET];                     // CSR: src node per slot

// ---------------- GEMM: H[n][c] = sum_k X[n][k] * W[k][c] ----------------
__global__ __launch_bounds__(256) void gemm_kernel(
    const float* __restrict__ X, const float* __restrict__ W,
    float* __restrict__ H, int nrows)
{
    __shared__ float sX[64][33];
    __shared__ float sW[32][128];

    const int tid  = threadIdx.x;
    const int row0 = blockIdx.x * 64;
    const int r0   = (tid >> 4) * 4;
    const int c0   = (tid & 15) * 8;

    float acc[4][8];
#pragma unroll
    for (int i = 0; i < 4; i++)
#pragma unroll
        for (int j = 0; j < 8; j++) acc[i][j] = 0.f;

    for (int k0 = 0; k0 < 128; k0 += 32) {
#pragma unroll
        for (int j = 0; j < 8; j++) {
            int idx = j * 256 + tid;
            int r = idx >> 5, k = idx & 31;
            int gr = row0 + r;
            sX[r][k] = (gr < nrows) ? X[(size_t)gr * 128 + k0 + k] : 0.f;
        }
#pragma unroll
        for (int j = 0; j < 16; j++) {
            int idx = j * 256 + tid;
            int k = idx >> 7, c = idx & 127;
            sW[k][c] = W[(size_t)(k0 + k) * 128 + c];
        }
        __syncthreads();

#pragma unroll
        for (int k = 0; k < 32; k++) {
            float4 wa = *(const float4*)&sW[k][c0];
            float4 wb = *(const float4*)&sW[k][c0 + 4];
            float xv[4];
#pragma unroll
            for (int i = 0; i < 4; i++) xv[i] = sX[r0 + i][k];
#pragma unroll
            for (int i = 0; i < 4; i++) {
                acc[i][0] += xv[i] * wa.x; acc[i][1] += xv[i] * wa.y;
                acc[i][2] += xv[i] * wa.z; acc[i][3] += xv[i] * wa.w;
                acc[i][4] += xv[i] * wb.x; acc[i][5] += xv[i] * wb.y;
                acc[i][6] += xv[i] * wb.z; acc[i][7] += xv[i] * wb.w;
            }
        }
        __syncthreads();
    }

#pragma unroll
    for (int i = 0; i < 4; i++) {
        int gr = row0 + r0 + i;
        if (gr < nrows) {
            *(float4*)&H[(size_t)gr * 128 + c0]     = make_float4(acc[i][0], acc[i][1], acc[i][2], acc[i][3]);
            *(float4*)&H[(size_t)gr * 128 + c0 + 4] = make_float4(acc[i][4], acc[i][5], acc[i][6], acc[i][7]);
        }
    }
}

// ---------------- per-node attention dot products ----------------
__global__ __launch_bounds__(256) void dots_kernel(
    const float* __restrict__ asrc, const float* __restrict__ adst)
{
    int warp = (blockIdx.x * blockDim.x + threadIdx.x) >> 5;
    int lane = threadIdx.x & 31;
    if (warp >= NN) return;
    float4 h4 = ((const float4*)g_h)[(size_t)warp * 32 + lane];
    float4 a4 = ((const float4*)asrc)[lane];
    float4 b4 = ((const float4*)adst)[lane];
    float ps = h4.x * a4.x + h4.y * a4.y + h4.z * a4.z + h4.w * a4.w;
    float pd = h4.x * b4.x + h4.y * b4.y + h4.z * b4.z + h4.w * b4.w;
#pragma unroll
    for (int o = 16; o; o >>= 1) {
        ps += __shfl_down_sync(0xffffffffu, ps, o);
        pd += __shfl_down_sync(0xffffffffu, pd, o);
    }
    if (lane == 0) { g_hs[warp] = ps; g_hd[warp] = pd; }
}

// ================= CSR build (once per launch) =================
__global__ __launch_bounds__(256) void csr_init_kernel()
{
    int i = blockIdx.x * blockDim.x + threadIdx.x;
    if (i < NN) { g_cnt[i] = 1; g_fill[i] = 0; }   // cnt=1 accounts for the self loop
    if (i == 0) g_rowoff[0] = 0;
}

__global__ __launch_bounds__(256) void csr_hist_kernel(const int* __restrict__ edst)
{
    int t = blockIdx.x * blockDim.x + threadIdx.x;
    if (t < EE) atomicAdd(&g_cnt[edst[t]], 1);
}

__device__ __forceinline__ int block_incl_scan_256(int v, int tid)
{
    int lane = tid & 31, w = tid >> 5;
#pragma unroll
    for (int o = 1; o < 32; o <<= 1) {
        int n = __shfl_up_sync(0xffffffffu, v, o);
        if (lane >= o) v += n;
    }
    __shared__ int wsum[8];
    if (lane == 31) wsum[w] = v;
    __syncthreads();
    if (tid < 8) {
        int x = wsum[tid];
#pragma unroll
        for (int o = 1; o < 8; o <<= 1) {
            int n = __shfl_up_sync(0xffu, x, o);
            if (tid >= o) x += n;
        }
        wsum[tid] = x;
    }
    __syncthreads();
    if (w > 0) v += wsum[w - 1];
    return v;
}

__global__ __launch_bounds__(256) void scan_block_kernel()
{
    int t = threadIdx.x, b = blockIdx.x;
    int i = b * 256 + t;
    int v = (i < NN) ? g_cnt[i] : 0;
    v = block_incl_scan_256(v, t);
    if (i < NN) g_rowoff[i + 1] = v;
    if (t == 255) g_bsum[b] = v;
}

__global__ __launch_bounds__(256) void scan_tops_kernel()
{
    int t = threadIdx.x;
    int v = (t < NB) ? g_bsum[t] : 0;
    v = block_incl_scan_256(v, t);
    if (t < NB) g_bsum[t] = v;
}

__global__ __launch_bounds__(256) void scan_add_kernel()
{
    int t = threadIdx.x, b = blockIdx.x;
    int i = b * 256 + t;
    if (b > 0 && i < NN) g_rowoff[i + 1] += g_bsum[b - 1];
}

__global__ __launch_bounds__(256) void csr_scatter_kernel(
    const int* __restrict__ esrc, const int* __restrict__ edst)
{
    int t = blockIdx.x * blockDim.x + threadIdx.x;
    if (t >= ET) return;
    int s, d;
    if (t < EE) { s = esrc[t]; d = edst[t]; }
    else        { s = t - EE; d = s; }
    int pos = g_rowoff[d] + atomicAdd(&g_fill[d], 1);
    g_csr[pos] = s;
}

// ========== fused: score + softmax + aggregate + bias + BN + ReLU ==========
// one warp per destination node
__global__ __launch_bounds__(256) void agg_kernel(
    float* __restrict__ outbuf,
    const float* __restrict__ bias,  const float* __restrict__ gamma,
    const float* __restrict__ beta,  const float* __restrict__ mean,
    const float* __restrict__ var)
{
    int node = (int)(((size_t)blockIdx.x * blockDim.x + threadIdx.x) >> 5);
    int lane = threadIdx.x & 31;
    if (node >= NN) return;

    const int off = g_rowoff[node];
    const int end = g_rowoff[node + 1];
    const float hd_d = g_hd[node];

    // pass 1: segment max of leaky_relu(hs[src] + hd[dst])
    float m = -CUDART_INF_F;
    for (int base = off; base < end; base += 32) {
        int i = base + lane;
        if (i < end) {
            int s = g_csr[i];
            float e = g_hs[s] + hd_d;
            e = e > 0.f ? e : SLOPE * e;
            m = fmaxf(m, e);
        }
    }
#pragma unroll
    for (int o = 16; o; o >>= 1) m = fmaxf(m, __shfl_xor_sync(0xffffffffu, m, o));

    // pass 2: exp-sum + weighted feature accumulation
    float ssum = 0.f;
    float4 acc = make_float4(0.f, 0.f, 0.f, 0.f);
    for (int base = off; base < end; base += 32) {
        int rem = end - base; if (rem > 32) rem = 32;
        int i = base + lane;
        int s = 0; float ee = 0.f;
        if (lane < rem) {
            s = g_csr[i];
            float e = g_hs[s] + hd_d;
            e = e > 0.f ? e : SLOPE * e;
            ee = __expf(e - m);
            ssum += ee;
        }
        if (rem == 32) {
#pragma unroll 8
            for (int j = 0; j < 32; j++) {
                int   sj  = __shfl_sync(0xffffffffu, s,  j);
                float eej = __shfl_sync(0xffffffffu, ee, j);
                float4 h4 = ((const float4*)g_h)[(size_t)sj * 32 + lane];
                acc.x += eej * h4.x; acc.y += eej * h4.y;
                acc.z += eej * h4.z; acc.w += eej * h4.w;
            }
        } else {
            for (int j = 0; j < rem; j++) {
                int   sj  = __shfl_sync(0xffffffffu, s,  j);
                float eej = __shfl_sync(0xffffffffu, ee, j);
                float4 h4 = ((const float4*)g_h)[(size_t)sj * 32 + lane];
                acc.x += eej * h4.x; acc.y += eej * h4.y;
                acc.z += eej * h4.z; acc.w += eej * h4.w;
            }
        }
    }
#pragma unroll
    for (int o = 16; o; o >>= 1) ssum += __shfl_xor_sync(0xffffffffu, ssum, o);
    float inv = 1.f / ssum;

    // epilogue: + bias, BN(eval), ReLU  (out = (agg+b-mean)*sc + beta)
    float4 ga = ((const float4*)gamma)[lane];
    float4 va = ((const float4*)var)[lane];
    float4 bi = ((const float4*)bias)[lane];
    float4 mu = ((const float4*)mean)[lane];
    float4 be = ((const float4*)beta)[lane];
    float4 sc, sh, o4;
    sc.x = ga.x * rsqrtf(va.x + BN_EPS); sh.x = (bi.x - mu.x) * sc.x + be.x;
    sc.y = ga.y * rsqrtf(va.y + BN_EPS); sh.y = (bi.y - mu.y) * sc.y + be.y;
    sc.z = ga.z * rsqrtf(va.z + BN_EPS); sh.z = (bi.z - mu.z) * sc.z + be.z;
    sc.w = ga.w * rsqrtf(va.w + BN_EPS); sh.w = (bi.w - mu.w) * sc.w + be.w;
    o4.x = fmaxf(fmaf(acc.x * inv, sc.x, sh.x), 0.f);
    o4.y = fmaxf(fmaf(acc.y * inv, sc.y, sh.y), 0.f);
    o4.z = fmaxf(fmaf(acc.z * inv, sc.z, sh.z), 0.f);
    o4.w = fmaxf(fmaf(acc.w * inv, sc.w, sh.w), 0.f);
    ((float4*)outbuf)[(size_t)node * 32 + lane] = o4;
}

// ---------------- host orchestration ----------------
static void run_layer(const float* x_in, float* agg_out, float* p_h,
                      const float* W, const float* asrc, const float* adst,
                      const float* bias, const float* gamma, const float* beta,
                      const float* mean, const float* var)
{
    gemm_kernel<<<(NN + 63) / 64, 256>>>(x_in, W, p_h, NN);
    dots_kernel<<<(NN * 32 + 255) / 256, 256>>>(asrc, adst);
    agg_kernel<<<(NN * 32 + 255) / 256, 256>>>(agg_out, bias, gamma, beta, mean, var);
}

extern "C" void kernel_launch(void* const* d_in, const int* in_sizes, int n_in,
                              void* d_out, int out_size)
{
    const float* x     = (const float*)d_in[0];
    const int*   eidx  = (const int*)d_in[1];     // int32: jax default (x64 disabled)
    const float* Ws    = (const float*)d_in[2];
    const float* a_src = (const float*)d_in[3];
    const float* a_dst = (const float*)d_in[4];
    const float* bias  = (const float*)d_in[5];
    const float* gamma = (const float*)d_in[6];
    const float* beta  = (const float*)d_in[7];
    const float* mean  = (const float*)d_in[8];
    const float* var   = (const float*)d_in[9];
    float*       out   = (float*)d_out;

    const int* esrc = eidx;
    const int* edst = eidx + EE;

    float* p_h;  cudaGetSymbolAddress((void**)&p_h, g_h);
    float* p_x1; cudaGetSymbolAddress((void**)&p_x1, g_x1);

    // CSR build (edges identical for both layers)
    csr_init_kernel<<<(NN + 255) / 256, 256>>>();
    csr_hist_kernel<<<(EE + 255) / 256, 256>>>(edst);
    scan_block_kernel<<<NB, 256>>>();
    scan_tops_kernel<<<1, 256>>>();
    scan_add_kernel<<<NB, 256>>>();
    csr_scatter_kernel<<<(ET + 255) / 256, 256>>>(esrc, edst);

    // layer 0: x -> g_x1
    run_layer(x, p_x1, p_h, Ws, a_src, a_dst, bias, gamma, beta, mean, var);
    // layer 1: g_x1 -> out
    run_layer(p_x1, out, p_h,
              Ws + DD * DD, a_src + DD, a_dst + DD, bias + DD,
              gamma + DD, beta + DD, mean + DD, var + DD);
}

// round 6
// speedup vs baseline: 1.3004x; 1.3004x over previous
#include <cuda_runtime.h>
#include <math_constants.h>

#define NN 50000
#define EE 800000
#define DD 128
#define ET (EE + NN)
#define NB ((NN + 255) / 256)
#define BN_EPS 1e-12f
#define SLOPE 0.2f
#define KT 16          // k-tile for GEMM
#define SKEW(c) ((c) + 4 * ((c) >> 5))   // injective, 4-aligned; max p = 127+12 = 139

// ---------------- scratch (static device globals; no allocation) ----------------
__device__ __align__(16) float g_h [NN * DD];
__device__ __align__(16) float g_x1[NN * DD];
__device__ float g_hs[NN];
__device__ float g_hd[NN];
__device__ int   g_cnt[NN];
__device__ int   g_rowoff[NN + 1];
__device__ int   g_fill[NN];
__device__ int   g_bsum[256];
__device__ int   g_csr[ET];

// ============ GEMM (128x128 tile, 8x8/thread, FFMA2) + fused attention dots ============
__global__ __launch_bounds__(256) void gemm_dots_kernel(
    const float* __restrict__ X, const float* __restrict__ W,
    float* __restrict__ H,
    const float* __restrict__ asrc, const float* __restrict__ adst)
{
    __shared__ float sXT[KT][132];   // transposed X tile: [k][row]
    __shared__ float sW [KT][140];   // W tile, skewed: phys col = SKEW(c)

    const int tid  = threadIdx.x;
    const int row0 = blockIdx.x * 128;
    const int ty   = tid >> 4;           // 0..15 -> 8 rows each
    const int tx   = tid & 15;           // 0..15 -> 8 cols each
    const int r0   = ty * 8;
    const int c0   = tx * 8;
    const int p0   = SKEW(c0);           // 8 contiguous floats (c0..c0+7 share the same skew group)

    unsigned long long accp[8][4];       // 8 rows x 4 col-pairs, packed f32x2
#pragma unroll
    for (int i = 0; i < 8; i++)
#pragma unroll
        for (int j = 0; j < 4; j++) accp[i][j] = 0ull;

    for (int k0 = 0; k0 < 128; k0 += KT) {
        // stage X transposed: 128 rows x 16 k
#pragma unroll
        for (int it = 0; it < 2; it++) {
            int e  = it * 1024 + tid * 4;
            int r  = e >> 4;
            int kk = e & 15;
            int gr = row0 + r;
            float4 v = make_float4(0.f, 0.f, 0.f, 0.f);
            if (gr < NN) v = *(const float4*)&X[(size_t)gr * 128 + k0 + kk];
            sXT[kk + 0][r] = v.x; sXT[kk + 1][r] = v.y;
            sXT[kk + 2][r] = v.z; sXT[kk + 3][r] = v.w;
        }
        // stage W skewed: 16 k x 128 c
#pragma unroll
        for (int it = 0; it < 2; it++) {
            int e = it * 1024 + tid * 4;
            int k = e >> 7;
            int c = e & 127;
            float4 v = *(const float4*)&W[(size_t)(k0 + k) * 128 + c];
            *(float4*)&sW[k][SKEW(c)] = v;
        }
        __syncthreads();

#pragma unroll
        for (int k = 0; k < KT; k++) {
            float xv[8];
            *(float4*)&xv[0] = *(const float4*)&sXT[k][r0];
            *(float4*)&xv[4] = *(const float4*)&sXT[k][r0 + 4];
            ulonglong2 wA = *(const ulonglong2*)&sW[k][p0];
            ulonglong2 wB = *(const ulonglong2*)&sW[k][p0 + 4];
#pragma unroll
            for (int i = 0; i < 8; i++) {
                unsigned long long xx;
                asm("mov.b64 %0, {%1, %1};" : "=l"(xx) : "f"(xv[i]));
                asm("fma.rn.f32x2 %0, %1, %2, %0;" : "+l"(accp[i][0]) : "l"(xx), "l"(wA.x));
                asm("fma.rn.f32x2 %0, %1, %2, %0;" : "+l"(accp[i][1]) : "l"(xx), "l"(wA.y));
                asm("fma.rn.f32x2 %0, %1, %2, %0;" : "+l"(accp[i][2]) : "l"(xx), "l"(wB.x));
                asm("fma.rn.f32x2 %0, %1, %2, %0;" : "+l"(accp[i][3]) : "l"(xx), "l"(wB.y));
            }
        }
        __syncthreads();
    }

    // unpack accumulators
    float h[8][8];
#pragma unroll
    for (int i = 0; i < 8; i++)
#pragma unroll
        for (int j = 0; j < 4; j++)
            asm("mov.b64 {%0, %1}, %2;" : "=f"(h[i][2 * j]), "=f"(h[i][2 * j + 1]) : "l"(accp[i][j]));

    // attention-dot vectors for this thread's 8 columns
    float av[8], bv[8];
    *(float4*)&av[0] = *(const float4*)&asrc[c0];
    *(float4*)&av[4] = *(const float4*)&asrc[c0 + 4];
    *(float4*)&bv[0] = *(const float4*)&adst[c0];
    *(float4*)&bv[4] = *(const float4*)&adst[c0 + 4];

#pragma unroll
    for (int i = 0; i < 8; i++) {
        int gr = row0 + r0 + i;
        if (gr < NN) {
            *(float4*)&H[(size_t)gr * 128 + c0]     = make_float4(h[i][0], h[i][1], h[i][2], h[i][3]);
            *(float4*)&H[(size_t)gr * 128 + c0 + 4] = make_float4(h[i][4], h[i][5], h[i][6], h[i][7]);
        }
        float ps = 0.f, pd = 0.f;
#pragma unroll
        for (int j = 0; j < 8; j++) { ps += h[i][j] * av[j]; pd += h[i][j] * bv[j]; }
#pragma unroll
        for (int o = 1; o < 16; o <<= 1) {
            ps += __shfl_xor_sync(0xffffffffu, ps, o);
            pd += __shfl_xor_sync(0xffffffffu, pd, o);
        }
        if (tx == 0 && gr < NN) { g_hs[gr] = ps; g_hd[gr] = pd; }
    }
}

// ================= CSR build (once per launch) =================
__global__ __launch_bounds__(256) void csr_init_kernel()
{
    int i = blockIdx.x * blockDim.x + threadIdx.x;
    if (i < NN) { g_cnt[i] = 1; g_fill[i] = 0; }   // self loop
    if (i == 0) g_rowoff[0] = 0;
}

__global__ __launch_bounds__(256) void csr_hist_kernel(const int* __restrict__ edst)
{
    int t = blockIdx.x * blockDim.x + threadIdx.x;
    if (t < EE) atomicAdd(&g_cnt[edst[t]], 1);
}

__device__ __forceinline__ int block_incl_scan_256(int v, int tid)
{
    int lane = tid & 31, w = tid >> 5;
#pragma unroll
    for (int o = 1; o < 32; o <<= 1) {
        int n = __shfl_up_sync(0xffffffffu, v, o);
        if (lane >= o) v += n;
    }
    __shared__ int wsum[8];
    if (lane == 31) wsum[w] = v;
    __syncthreads();
    if (tid < 8) {
        int x = wsum[tid];
#pragma unroll
        for (int o = 1; o < 8; o <<= 1) {
            int n = __shfl_up_sync(0xffu, x, o);
            if (tid >= o) x += n;
        }
        wsum[tid] = x;
    }
    __syncthreads();
    if (w > 0) v += wsum[w - 1];
    return v;
}

__global__ __launch_bounds__(256) void scan_block_kernel()
{
    int t = threadIdx.x, b = blockIdx.x;
    int i = b * 256 + t;
    int v = (i < NN) ? g_cnt[i] : 0;
    v = block_incl_scan_256(v, t);
    if (i < NN) g_rowoff[i + 1] = v;
    if (t == 255) g_bsum[b] = v;
}

__global__ __launch_bounds__(256) void scan_tops_kernel()
{
    int t = threadIdx.x;
    int v = (t < NB) ? g_bsum[t] : 0;
    v = block_incl_scan_256(v, t);
    if (t < NB) g_bsum[t] = v;
}

__global__ __launch_bounds__(256) void scan_add_kernel()
{
    int t = threadIdx.x, b = blockIdx.x;
    int i = b * 256 + t;
    if (b > 0 && i < NN) g_rowoff[i + 1] += g_bsum[b - 1];
}

__global__ __launch_bounds__(256) void csr_scatter_kernel(
    const int* __restrict__ esrc, const int* __restrict__ edst)
{
    int t = blockIdx.x * blockDim.x + threadIdx.x;
    if (t >= ET) return;
    int s, d;
    if (t < EE) { s = esrc[t]; d = edst[t]; }
    else        { s = t - EE; d = s; }
    int pos = g_rowoff[d] + atomicAdd(&g_fill[d], 1);
    g_csr[pos] = s;
}

// ========== fused: score + softmax + aggregate + bias + BN + ReLU ==========
__global__ __launch_bounds__(256) void agg_kernel(
    float* __restrict__ outbuf,
    const float* __restrict__ bias,  const float* __restrict__ gamma,
    const float* __restrict__ beta,  const float* __restrict__ mean,
    const float* __restrict__ var)
{
    int node = (int)(((size_t)blockIdx.x * blockDim.x + threadIdx.x) >> 5);
    int lane = threadIdx.x & 31;
    if (node >= NN) return;

    const int off = g_rowoff[node];
    const int end = g_rowoff[node + 1];
    const float hd_d = g_hd[node];

    float m = -CUDART_INF_F;
    for (int base = off; base < end; base += 32) {
        int i = base + lane;
        if (i < end) {
            int s = g_csr[i];
            float e = g_hs[s] + hd_d;
            e = e > 0.f ? e : SLOPE * e;
            m = fmaxf(m, e);
        }
    }
#pragma unroll
    for (int o = 16; o; o >>= 1) m = fmaxf(m, __shfl_xor_sync(0xffffffffu, m, o));

    float ssum = 0.f;
    float4 acc = make_float4(0.f, 0.f, 0.f, 0.f);
    for (int base = off; base < end; base += 32) {
        int rem = end - base; if (rem > 32) rem = 32;
        int i = base + lane;
        int s = 0; float ee = 0.f;
        if (lane < rem) {
            s = g_csr[i];
            float e = g_hs[s] + hd_d;
            e = e > 0.f ? e : SLOPE * e;
            ee = __expf(e - m);
            ssum += ee;
        }
        if (rem == 32) {
#pragma unroll 8
            for (int j = 0; j < 32; j++) {
                int   sj  = __shfl_sync(0xffffffffu, s,  j);
                float eej = __shfl_sync(0xffffffffu, ee, j);
                float4 h4 = ((const float4*)g_h)[(size_t)sj * 32 + lane];
                acc.x += eej * h4.x; acc.y += eej * h4.y;
                acc.z += eej * h4.z; acc.w += eej * h4.w;
            }
        } else {
            for (int j = 0; j < rem; j++) {
                int   sj  = __shfl_sync(0xffffffffu, s,  j);
                float eej = __shfl_sync(0xffffffffu, ee, j);
                float4 h4 = ((const float4*)g_h)[(size_t)sj * 32 + lane];
                acc.x += eej * h4.x; acc.y += eej * h4.y;
                acc.z += eej * h4.z; acc.w += eej * h4.w;
            }
        }
    }
#pragma unroll
    for (int o = 16; o; o >>= 1) ssum += __shfl_xor_sync(0xffffffffu, ssum, o);
    float inv = 1.f / ssum;

    float4 ga = ((const float4*)gamma)[lane];
    float4 va = ((const float4*)var)[lane];
    float4 bi = ((const float4*)bias)[lane];
    float4 mu = ((const float4*)mean)[lane];
    float4 be = ((const float4*)beta)[lane];
    float4 sc, sh, o4;
    sc.x = ga.x * rsqrtf(va.x + BN_EPS); sh.x = (bi.x - mu.x) * sc.x + be.x;
    sc.y = ga.y * rsqrtf(va.y + BN_EPS); sh.y = (bi.y - mu.y) * sc.y + be.y;
    sc.z = ga.z * rsqrtf(va.z + BN_EPS); sh.z = (bi.z - mu.z) * sc.z + be.z;
    sc.w = ga.w * rsqrtf(va.w + BN_EPS); sh.w = (bi.w - mu.w) * sc.w + be.w;
    o4.x = fmaxf(fmaf(acc.x * inv, sc.x, sh.x), 0.f);
    o4.y = fmaxf(fmaf(acc.y * inv, sc.y, sh.y), 0.f);
    o4.z = fmaxf(fmaf(acc.z * inv, sc.z, sh.z), 0.f);
    o4.w = fmaxf(fmaf(acc.w * inv, sc.w, sh.w), 0.f);
    ((float4*)outbuf)[(size_t)node * 32 + lane] = o4;
}

// ---------------- host orchestration ----------------
static void run_layer(const float* x_in, float* agg_out, float* p_h,
                      const float* W, const float* asrc, const float* adst,
                      const float* bias, const float* gamma, const float* beta,
                      const float* mean, const float* var)
{
    gemm_dots_kernel<<<(NN + 127) / 128, 256>>>(x_in, W, p_h, asrc, adst);
    agg_kernel<<<(NN * 32 + 255) / 256, 256>>>(agg_out, bias, gamma, beta, mean, var);
}

extern "C" void kernel_launch(void* const* d_in, const int* in_sizes, int n_in,
                              void* d_out, int out_size)
{
    const float* x     = (const float*)d_in[0];
    const int*   eidx  = (const int*)d_in[1];
    const float* Ws    = (const float*)d_in[2];
    const float* a_src = (const float*)d_in[3];
    const float* a_dst = (const float*)d_in[4];
    const float* bias  = (const float*)d_in[5];
    const float* gamma = (const float*)d_in[6];
    const float* beta  = (const float*)d_in[7];
    const float* mean  = (const float*)d_in[8];
    const float* var   = (const float*)d_in[9];
    float*       out   = (float*)d_out;

    const int* esrc = eidx;
    const int* edst = eidx + EE;

    float* p_h;  cudaGetSymbolAddress((void**)&p_h, g_h);
    float* p_x1; cudaGetSymbolAddress((void**)&p_x1, g_x1);

    csr_init_kernel<<<(NN + 255) / 256, 256>>>();
    csr_hist_kernel<<<(EE + 255) / 256, 256>>>(edst);
    scan_block_kernel<<<NB, 256>>>();
    scan_tops_kernel<<<1, 256>>>();
    scan_add_kernel<<<NB, 256>>>();
    csr_scatter_kernel<<<(ET + 255) / 256, 256>>>(esrc, edst);

    run_layer(x, p_x1, p_h, Ws, a_src, a_dst, bias, gamma, beta, mean, var);
    run_layer(p_x1, out, p_h,
              Ws + DD * DD, a_src + DD, a_dst + DD, bias + DD,
              gamma + DD, beta + DD, mean + DD, var + DD);
}